// round 1
// baseline (speedup 1.0000x reference)
#include <cuda_runtime.h>
#include <cuda_bf16.h>
#include <math.h>

// Shapes
#define B_ 8
#define N_ 512
#define M_ 6
#define ED_ 8
#define SRC_ 64
#define OBS_ 32
#define D_ 16
#define H_ 64

// Scratch (no allocations allowed)
__device__ float g_x[B_ * N_ * D_];    // x = obs_all @ w_obs + b_obs
__device__ float g_y2[B_ * N_ * D_];   // y2 = x @ W2 (wemb[1] rows 16..31)
__device__ float g_sel[B_ * M_ * D_];  // selected + masked x_adapt rows

// ---------------------------------------------------------------------------
// Kernel 1: per-node embeddings. One thread per (b,n) row.
// ---------------------------------------------------------------------------
__global__ void k_embed(const float* __restrict__ obs_all,
                        const float* __restrict__ w_obs,
                        const float* __restrict__ b_obs,
                        const float* __restrict__ ge_wemb) {
    __shared__ float s_wobs[OBS_ * D_];  // 512
    __shared__ float s_w2[D_ * D_];      // 256
    for (int t = threadIdx.x; t < OBS_ * D_; t += blockDim.x) s_wobs[t] = w_obs[t];
    for (int t = threadIdx.x; t < D_ * D_; t += blockDim.x)
        s_w2[t] = ge_wemb[768 + 256 + t];  // wemb[1][16+k][d], contiguous
    __syncthreads();

    int row = blockIdx.x * blockDim.x + threadIdx.x;
    if (row >= B_ * N_) return;

    float o[OBS_];
    const float4* op = reinterpret_cast<const float4*>(obs_all + (size_t)row * OBS_);
#pragma unroll
    for (int q = 0; q < OBS_ / 4; q++) {
        float4 v = op[q];
        o[4 * q] = v.x; o[4 * q + 1] = v.y; o[4 * q + 2] = v.z; o[4 * q + 3] = v.w;
    }
    float x[D_];
#pragma unroll
    for (int d = 0; d < D_; d++) {
        float acc = b_obs[d];
#pragma unroll
        for (int s = 0; s < OBS_; s++) acc += o[s] * s_wobs[s * D_ + d];
        x[d] = acc;
        g_x[row * D_ + d] = acc;
    }
#pragma unroll
    for (int d = 0; d < D_; d++) {
        float acc = 0.f;
#pragma unroll
        for (int k = 0; k < D_; k++) acc += x[k] * s_w2[k * D_ + d];
        g_y2[row * D_ + d] = acc;
    }
}

// ---------------------------------------------------------------------------
// Kernel 2: one block per selected (b,m) pair. 48 blocks, 256 threads.
// Computes x_adapt row i (i = road_neighbor_idxs[ridxs[b]][m]) with i=1
// weights only (i=0 iteration of the reference loop is dead), applies mask.
// ---------------------------------------------------------------------------
__global__ void k_row(const float* __restrict__ A,
                      const float* __restrict__ PA,
                      const float* __restrict__ ea,
                      const int* __restrict__ ridxs,
                      const int* __restrict__ nbr_idx,
                      const int* __restrict__ nbr_mask,
                      const float* __restrict__ res_w,
                      const float* __restrict__ res_b,
                      const float* __restrict__ ge_we,
                      const float* __restrict__ ge_be,
                      const float* __restrict__ ge_wemb,
                      const float* __restrict__ ge_bemb) {
    const int b = blockIdx.x / M_;
    const int m = blockIdx.x % M_;
    const int r = ridxs[b];
    const int i = nbr_idx[r * M_ + m];
    const int msk = nbr_mask[r * M_ + m];
    const int tid = threadIdx.x;

    if (msk == 0) {  // whole block takes this branch; no barrier divergence
        if (tid < D_) g_sel[b * (M_ * D_) + m * D_ + tid] = -1.0f;
        return;
    }

    // Accumulate deg (1), eagg (8), av (16) over j.
    float acc[25];
#pragma unroll
    for (int q = 0; q < 25; q++) acc[q] = 0.f;

    for (int j = tid; j < N_; j += 256) {
        float a = A[i * N_ + j] + PA[i * N_ + j];
        acc[0] += a;
        const float4* ep = reinterpret_cast<const float4*>(
            ea + ((((size_t)b * N_ + i) * N_ + j) * ED_));
        float4 e0 = ep[0], e1 = ep[1];
        acc[1] += a * e0.x; acc[2] += a * e0.y; acc[3] += a * e0.z; acc[4] += a * e0.w;
        acc[5] += a * e1.x; acc[6] += a * e1.y; acc[7] += a * e1.z; acc[8] += a * e1.w;
        const float4* yp = reinterpret_cast<const float4*>(g_y2 + ((size_t)b * N_ + j) * D_);
#pragma unroll
        for (int q = 0; q < 4; q++) {
            float4 v = yp[q];
            acc[9 + 4 * q]     += a * v.x;
            acc[9 + 4 * q + 1] += a * v.y;
            acc[9 + 4 * q + 2] += a * v.z;
            acc[9 + 4 * q + 3] += a * v.w;
        }
    }

    // warp reduce
#pragma unroll
    for (int q = 0; q < 25; q++)
#pragma unroll
        for (int off = 16; off > 0; off >>= 1)
            acc[q] += __shfl_down_sync(0xffffffffu, acc[q], off);

    __shared__ float sred[8 * 25];
    __shared__ float fin[25];
    __shared__ float tk[D_];
    const int warp = tid >> 5, lane = tid & 31;
    if (lane == 0)
#pragma unroll
        for (int q = 0; q < 25; q++) sred[warp * 25 + q] = acc[q];
    __syncthreads();
    if (tid < 25) {
        float s = 0.f;
#pragma unroll
        for (int w = 0; w < 8; w++) s += sred[w * 25 + tid];
        fin[tid] = s;
    }
    __syncthreads();

    // t[k] = sum_e eagg[e]*we1[e][k] + deg*be1[k]   (folds be@W3 bias path)
    if (tid < D_) {
        float s = fin[0] * ge_be[D_ + tid];
#pragma unroll
        for (int e = 0; e < ED_; e++) s += fin[1 + e] * ge_we[ED_ * D_ + e * D_ + tid];
        tk[tid] = s;
    }
    __syncthreads();

    if (tid < D_) {
        const int d = tid;
        const float deg = fin[0];
        float val = res_b[D_ + d];
        float xw1 = 0.f;
#pragma unroll
        for (int k = 0; k < D_; k++) {
            float xv = g_x[((size_t)b * N_ + i) * D_ + k];
            val += xv * res_w[256 + k * D_ + d];       // res_w[1]
            xw1 += xv * ge_wemb[768 + k * D_ + d];     // W1 = wemb[1][0:16]
        }
        float eproj = 0.f;
#pragma unroll
        for (int k = 0; k < D_; k++)
            eproj += tk[k] * ge_wemb[768 + 512 + k * D_ + d];  // W3 = wemb[1][32:48]
        val += deg * xw1 + fin[9 + d] + eproj + deg * ge_bemb[D_ + d];
        val = fmaxf(val, 0.0f);
        g_sel[b * (M_ * D_) + m * D_ + d] = val;
    }
}

// ---------------------------------------------------------------------------
// Kernel 3: fused head. One block, warp b handles batch b.
// ---------------------------------------------------------------------------
__global__ void k_head(const float* __restrict__ obs,
                       const float* __restrict__ w_src,
                       const float* __restrict__ b_src,
                       const float* __restrict__ gated_w,
                       const float* __restrict__ gated_b,
                       const float* __restrict__ bw1,
                       const float* __restrict__ bb1,
                       const float* __restrict__ bw2,
                       const float* __restrict__ bb2,
                       const float* __restrict__ act_w,
                       const float* __restrict__ act_b,
                       float* __restrict__ out) {
    const int b = threadIdx.x >> 5;
    const int lane = threadIdx.x & 31;
    __shared__ float cat[B_][192];
    __shared__ float h0[B_][D_];
    __shared__ float h1[B_][H_];
    __shared__ float h2[B_][H_];

    // obs_p = obs @ w_src + b_src  (96 outputs)
    for (int k = lane; k < 96; k += 32) {
        float s = b_src[k];
#pragma unroll 8
        for (int q = 0; q < SRC_; q++) s += obs[b * SRC_ + q] * w_src[q * 96 + k];
        cat[b][k] = s;
    }
    for (int k = lane; k < 96; k += 32) cat[b][96 + k] = g_sel[b * 96 + k];
    __syncwarp();

    // g = cat @ gated_w + gated_b ; h0 = gated * sigmoid(gate)
    {
        float s = gated_b[lane];
        for (int q = 0; q < 192; q++) s += cat[b][q] * gated_w[q * 32 + lane];
        float other = __shfl_sync(0xffffffffu, s, lane ^ 16);
        if (lane < D_) h0[b][lane] = s * (1.0f / (1.0f + expf(-other)));
    }
    __syncwarp();

    for (int k = lane; k < H_; k += 32) {
        float s = bb1[k];
#pragma unroll
        for (int d = 0; d < D_; d++) s += h0[b][d] * bw1[d * H_ + k];
        h1[b][k] = fmaxf(s, 0.0f);
    }
    __syncwarp();

    for (int k = lane; k < H_; k += 32) {
        float s = bb2[k];
#pragma unroll 8
        for (int j = 0; j < H_; j++) s += h1[b][j] * bw2[j * H_ + k];
        h2[b][k] = fmaxf(s, 0.0f);
    }
    __syncwarp();

    if (lane < M_) {
        float s = act_b[lane];
#pragma unroll 8
        for (int j = 0; j < H_; j++) s += h2[b][j] * act_w[j * M_ + lane];
        out[b * M_ + lane] = s;
    }
}

// ---------------------------------------------------------------------------
extern "C" void kernel_launch(void* const* d_in, const int* in_sizes, int n_in,
                              void* d_out, int out_size) {
    const float* obs       = (const float*)d_in[0];
    const float* obs_all   = (const float*)d_in[1];
    const float* edge      = (const float*)d_in[2];
    const int*   ridxs     = (const int*)  d_in[3];
    const int*   nbr_idx   = (const int*)  d_in[4];
    const int*   nbr_mask  = (const int*)  d_in[5];
    const float* A         = (const float*)d_in[6];
    const float* PA        = (const float*)d_in[7];
    const float* w_src     = (const float*)d_in[8];
    const float* b_src     = (const float*)d_in[9];
    const float* w_obs     = (const float*)d_in[10];
    const float* b_obs     = (const float*)d_in[11];
    const float* res_w     = (const float*)d_in[12];
    const float* res_b     = (const float*)d_in[13];
    const float* ge_we     = (const float*)d_in[14];
    const float* ge_be     = (const float*)d_in[15];
    const float* ge_wemb   = (const float*)d_in[16];
    const float* ge_bemb   = (const float*)d_in[17];
    const float* gated_w   = (const float*)d_in[18];
    const float* gated_b   = (const float*)d_in[19];
    const float* base_w1   = (const float*)d_in[20];
    const float* base_b1   = (const float*)d_in[21];
    const float* base_w2   = (const float*)d_in[22];
    const float* base_b2   = (const float*)d_in[23];
    const float* act_w     = (const float*)d_in[24];
    const float* act_b     = (const float*)d_in[25];
    float* out = (float*)d_out;

    k_embed<<<(B_ * N_ + 255) / 256, 256>>>(obs_all, w_obs, b_obs, ge_wemb);
    k_row<<<B_ * M_, 256>>>(A, PA, edge, ridxs, nbr_idx, nbr_mask,
                            res_w, res_b, ge_we, ge_be, ge_wemb, ge_bemb);
    k_head<<<1, 256>>>(obs, w_src, b_src, gated_w, gated_b,
                       base_w1, base_b1, base_w2, base_b2, act_w, act_b, out);
}

// round 2
// speedup vs baseline: 1.3386x; 1.3386x over previous
#include <cuda_runtime.h>
#include <cuda_bf16.h>
#include <math.h>

// Shapes
#define B_ 8
#define N_ 512
#define M_ 6
#define ED_ 8
#define SRC_ 64
#define OBS_ 32
#define D_ 16
#define H_ 64

// Scratch (no allocations allowed)
__device__ float g_sel[B_ * M_ * D_];   // selected + masked x_adapt rows
__device__ unsigned int g_count = 0;    // last-block-done counter (self-resetting)

// ---------------------------------------------------------------------------
// Single fused kernel. 48 blocks x 256 threads.
// Block (b,m): computes x_adapt row i = nbr_idx[ridxs[b]][m] using only the
// i=1 GNN weights (the i=0 loop iteration in the reference is dead code),
// via the linearity reformulation:
//   sum_j a_ij * (x@W2)[b,j] = (sum_j a_ij obs_all[b,j]) @ (w_obs@W2)
//                              + deg * (b_obs@W2)
// so no per-node embedding pass is needed. The last block to finish runs the
// gated-MLP head.
// ---------------------------------------------------------------------------
__global__ void __launch_bounds__(256, 1)
k_fused(const float* __restrict__ obs,
        const float* __restrict__ obs_all,
        const float* __restrict__ ea,
        const int* __restrict__ ridxs,
        const int* __restrict__ nbr_idx,
        const int* __restrict__ nbr_mask,
        const float* __restrict__ A,
        const float* __restrict__ PA,
        const float* __restrict__ w_src,
        const float* __restrict__ b_src,
        const float* __restrict__ w_obs,
        const float* __restrict__ b_obs,
        const float* __restrict__ res_w,
        const float* __restrict__ res_b,
        const float* __restrict__ ge_we,
        const float* __restrict__ ge_be,
        const float* __restrict__ ge_wemb,
        const float* __restrict__ ge_bemb,
        const float* __restrict__ gated_w,
        const float* __restrict__ gated_b,
        const float* __restrict__ bw1,
        const float* __restrict__ bb1,
        const float* __restrict__ bw2,
        const float* __restrict__ bb2,
        const float* __restrict__ act_w,
        const float* __restrict__ act_b,
        float* __restrict__ out) {
    const int b = blockIdx.x / M_;
    const int m = blockIdx.x % M_;
    const int tid = threadIdx.x;
    const int r = ridxs[b];
    const int i = nbr_idx[r * M_ + m];
    const int msk = nbr_mask[r * M_ + m];

    // wemb[1] sub-blocks (row-major (48,16), starting at offset 768)
    const float* W1 = ge_wemb + 768;         // rows 0..15
    const float* W2 = ge_wemb + 768 + 256;   // rows 16..31
    const float* W3 = ge_wemb + 768 + 512;   // rows 32..47

    __shared__ float sC[OBS_ * D_];   // w_obs @ W2  (32x16)
    __shared__ float sbW2[D_];        // b_obs @ W2
    __shared__ float sred[8 * 41];
    __shared__ float fin[41];         // [0]=deg [1..8]=eagg [9..40]=sobs
    __shared__ float stk[D_];
    __shared__ float sxi[D_];

    if (msk != 0) {  // msk is block-uniform; no divergent barriers
        // Precompute C = w_obs @ W2 and bW2 = b_obs @ W2
        for (int t = tid; t < OBS_ * D_; t += 256) {
            const int s = t >> 4, d = t & 15;
            float acc = 0.f;
#pragma unroll
            for (int k = 0; k < D_; k++) acc += w_obs[s * D_ + k] * W2[k * D_ + d];
            sC[t] = acc;
        }
        if (tid < D_) {
            float acc = 0.f;
#pragma unroll
            for (int k = 0; k < D_; k++) acc += b_obs[k] * W2[k * D_ + tid];
            sbW2[tid] = acc;
        }

        // Main reduction over j: deg, eagg[8], sobs[32]
        float acc[41];
#pragma unroll
        for (int q = 0; q < 41; q++) acc[q] = 0.f;

        for (int j = tid; j < N_; j += 256) {
            const float a = A[i * N_ + j] + PA[i * N_ + j];
            acc[0] += a;
            const float4* ep = reinterpret_cast<const float4*>(
                ea + ((((size_t)b * N_ + i) * N_ + j) * ED_));
            float4 e0 = ep[0], e1 = ep[1];
            acc[1] += a * e0.x; acc[2] += a * e0.y; acc[3] += a * e0.z; acc[4] += a * e0.w;
            acc[5] += a * e1.x; acc[6] += a * e1.y; acc[7] += a * e1.z; acc[8] += a * e1.w;
            const float4* op = reinterpret_cast<const float4*>(
                obs_all + ((size_t)b * N_ + j) * OBS_);
#pragma unroll
            for (int q = 0; q < OBS_ / 4; q++) {
                float4 v = op[q];
                acc[9 + 4 * q]     += a * v.x;
                acc[9 + 4 * q + 1] += a * v.y;
                acc[9 + 4 * q + 2] += a * v.z;
                acc[9 + 4 * q + 3] += a * v.w;
            }
        }

#pragma unroll
        for (int q = 0; q < 41; q++)
#pragma unroll
            for (int off = 16; off > 0; off >>= 1)
                acc[q] += __shfl_down_sync(0xffffffffu, acc[q], off);

        const int warp = tid >> 5, lane = tid & 31;
        if (lane == 0)
#pragma unroll
            for (int q = 0; q < 41; q++) sred[warp * 41 + q] = acc[q];
        __syncthreads();
        if (tid < 41) {
            float s = 0.f;
#pragma unroll
            for (int w = 0; w < 8; w++) s += sred[w * 41 + tid];
            fin[tid] = s;
        }
        __syncthreads();

        if (tid < D_) {
            // tk[k] = eagg @ we1 + deg*be1  (folds (.. + be)@W3 bias)
            float s = fin[0] * ge_be[D_ + tid];
#pragma unroll
            for (int e = 0; e < ED_; e++)
                s += fin[1 + e] * ge_we[ED_ * D_ + e * D_ + tid];
            stk[tid] = s;
            // xi[k] = obs_all[b,i,:] @ w_obs[:,k] + b_obs[k]
            float x = b_obs[tid];
            const float* orow = obs_all + ((size_t)b * N_ + i) * OBS_;
#pragma unroll
            for (int s2 = 0; s2 < OBS_; s2++) x += orow[s2] * w_obs[s2 * D_ + tid];
            sxi[tid] = x;
        }
        __syncwarp(0xffffffffu);

        if (tid < D_) {
            const int d = tid;
            const float deg = fin[0];
            float val = res_b[D_ + d] + deg * ge_bemb[D_ + d];
            float xw1 = 0.f;
#pragma unroll
            for (int k = 0; k < D_; k++) {
                val += sxi[k] * res_w[256 + k * D_ + d];  // res_w[1]
                xw1 += sxi[k] * W1[k * D_ + d];
            }
            val += deg * xw1;
            float av = deg * sbW2[d];
#pragma unroll
            for (int s = 0; s < OBS_; s++) av += fin[9 + s] * sC[s * D_ + d];
            val += av;
            float eproj = 0.f;
#pragma unroll
            for (int k = 0; k < D_; k++) eproj += stk[k] * W3[k * D_ + d];
            val += eproj;
            g_sel[b * (M_ * D_) + m * D_ + d] = fmaxf(val, 0.0f);
        }
    } else {
        if (tid < D_) g_sel[b * (M_ * D_) + m * D_ + tid] = -1.0f;
    }

    // ---- last-block-done: run the head ----
    __threadfence();
    __shared__ int is_last;
    if (tid == 0) {
        unsigned int c = atomicAdd(&g_count, 1u);
        is_last = (c == (unsigned int)(gridDim.x - 1));
        if (is_last) atomicExch(&g_count, 0u);  // reset for graph replay
    }
    __syncthreads();
    if (!is_last) return;

    // ===================== fused head (1 block, warp per b) =================
    {
        const int hb = tid >> 5;
        const int lane = tid & 31;
        __shared__ float cat[B_][192];
        __shared__ float h0[B_][D_];
        __shared__ float h1[B_][H_];
        __shared__ float h2[B_][H_];

        for (int k = lane; k < 96; k += 32) {
            float s = b_src[k];
#pragma unroll 8
            for (int q = 0; q < SRC_; q++) s += obs[hb * SRC_ + q] * w_src[q * 96 + k];
            cat[hb][k] = s;
        }
        for (int k = lane; k < 96; k += 32) cat[hb][96 + k] = g_sel[hb * 96 + k];
        __syncwarp();

        {
            float s = gated_b[lane];
            for (int q = 0; q < 192; q++) s += cat[hb][q] * gated_w[q * 32 + lane];
            float other = __shfl_sync(0xffffffffu, s, lane ^ 16);
            if (lane < D_) h0[hb][lane] = s * (1.0f / (1.0f + expf(-other)));
        }
        __syncwarp();

        for (int k = lane; k < H_; k += 32) {
            float s = bb1[k];
#pragma unroll
            for (int d = 0; d < D_; d++) s += h0[hb][d] * bw1[d * H_ + k];
            h1[hb][k] = fmaxf(s, 0.0f);
        }
        __syncwarp();

        for (int k = lane; k < H_; k += 32) {
            float s = bb2[k];
#pragma unroll 8
            for (int j = 0; j < H_; j++) s += h1[hb][j] * bw2[j * H_ + k];
            h2[hb][k] = fmaxf(s, 0.0f);
        }
        __syncwarp();

        if (lane < M_) {
            float s = act_b[lane];
#pragma unroll 8
            for (int j = 0; j < H_; j++) s += h2[hb][j] * act_w[j * M_ + lane];
            out[hb * M_ + lane] = s;
        }
    }
}

// ---------------------------------------------------------------------------
extern "C" void kernel_launch(void* const* d_in, const int* in_sizes, int n_in,
                              void* d_out, int out_size) {
    const float* obs       = (const float*)d_in[0];
    const float* obs_all   = (const float*)d_in[1];
    const float* edge      = (const float*)d_in[2];
    const int*   ridxs     = (const int*)  d_in[3];
    const int*   nbr_idx   = (const int*)  d_in[4];
    const int*   nbr_mask  = (const int*)  d_in[5];
    const float* A         = (const float*)d_in[6];
    const float* PA        = (const float*)d_in[7];
    const float* w_src     = (const float*)d_in[8];
    const float* b_src     = (const float*)d_in[9];
    const float* w_obs     = (const float*)d_in[10];
    const float* b_obs     = (const float*)d_in[11];
    const float* res_w     = (const float*)d_in[12];
    const float* res_b     = (const float*)d_in[13];
    const float* ge_we     = (const float*)d_in[14];
    const float* ge_be     = (const float*)d_in[15];
    const float* ge_wemb   = (const float*)d_in[16];
    const float* ge_bemb   = (const float*)d_in[17];
    const float* gated_w   = (const float*)d_in[18];
    const float* gated_b   = (const float*)d_in[19];
    const float* base_w1   = (const float*)d_in[20];
    const float* base_b1   = (const float*)d_in[21];
    const float* base_w2   = (const float*)d_in[22];
    const float* base_b2   = (const float*)d_in[23];
    const float* act_w     = (const float*)d_in[24];
    const float* act_b     = (const float*)d_in[25];
    float* out = (float*)d_out;

    k_fused<<<B_ * M_, 256>>>(obs, obs_all, edge, ridxs, nbr_idx, nbr_mask,
                              A, PA, w_src, b_src, w_obs, b_obs,
                              res_w, res_b, ge_we, ge_be, ge_wemb, ge_bemb,
                              gated_w, gated_b, base_w1, base_b1,
                              base_w2, base_b2, act_w, act_b, out);
}

// round 3
// speedup vs baseline: 1.5341x; 1.1460x over previous
#include <cuda_runtime.h>
#include <cuda_bf16.h>
#include <math.h>

// Shapes
#define B_ 8
#define N_ 512
#define M_ 6
#define ED_ 8
#define SRC_ 64
#define OBS_ 32
#define D_ 16
#define H_ 64
#define NW_ 16  // warps per block

__device__ float g_sel[B_ * M_ * D_];
__device__ unsigned int g_count = 0;

// ---------------------------------------------------------------------------
// One fused kernel: 48 blocks (one per selected (b,m) row) x 512 threads.
// Lane-transposed reduction: lane = feature dim, warp = j-slice.
// Last block through the atomic gate runs the gated-MLP head.
// ---------------------------------------------------------------------------
__global__ void __launch_bounds__(512, 1)
k_fused(const float* __restrict__ obs,
        const float* __restrict__ obs_all,
        const float* __restrict__ ea,
        const int* __restrict__ ridxs,
        const int* __restrict__ nbr_idx,
        const int* __restrict__ nbr_mask,
        const float* __restrict__ A,
        const float* __restrict__ PA,
        const float* __restrict__ w_src,
        const float* __restrict__ b_src,
        const float* __restrict__ w_obs,
        const float* __restrict__ b_obs,
        const float* __restrict__ res_w,
        const float* __restrict__ res_b,
        const float* __restrict__ ge_we,
        const float* __restrict__ ge_be,
        const float* __restrict__ ge_wemb,
        const float* __restrict__ ge_bemb,
        const float* __restrict__ gated_w,
        const float* __restrict__ gated_b,
        const float* __restrict__ bw1,
        const float* __restrict__ bb1,
        const float* __restrict__ bw2,
        const float* __restrict__ bb2,
        const float* __restrict__ act_w,
        const float* __restrict__ act_b,
        float* __restrict__ out) {
    const int b = blockIdx.x / M_;
    const int m = blockIdx.x % M_;
    const int tid = threadIdx.x;
    const int r = ridxs[b];
    const int i = nbr_idx[r * M_ + m];
    const int msk = nbr_mask[r * M_ + m];

    // wemb[1] sub-blocks (row-major (48,16), offset 768 = layer 1)
    const float* W1 = ge_wemb + 768;
    const float* W2 = ge_wemb + 768 + 256;
    const float* W3 = ge_wemb + 768 + 512;

    __shared__ float s_a[N_];            // adjacency row (A+PA)
    __shared__ float sC[OBS_ * D_];      // w_obs @ W2
    __shared__ float s_obs[NW_][33];     // per-warp partial sobs
    __shared__ float s_e[NW_][8];        // per-warp partial eagg
    __shared__ float s_deg[NW_];         // per-warp partial deg
    __shared__ float fin[41];            // [0]=deg [1..8]=eagg [9..40]=sobs
    __shared__ float stk[D_];
    __shared__ float sxi[D_];

    if (msk != 0) {  // block-uniform branch
        // stage adjacency row (coalesced)
        s_a[tid] = A[i * N_ + tid] + PA[i * N_ + tid];

        // sC[t] = (w_obs @ W2)[s,d]; 512 entries = exactly one per thread
        {
            const int s = tid >> 4, d = tid & 15;
            float acc = 0.f;
#pragma unroll
            for (int k = 0; k < D_; k++) acc += w_obs[s * D_ + k] * W2[k * D_ + d];
            sC[tid] = acc;
        }
        __syncthreads();

        const int w = tid >> 5, lane = tid & 31;
        float acc_obs = 0.f, acc_e = 0.f, acc_deg = 0.f;
        const float* obs_base = obs_all + ((size_t)b * N_) * OBS_ + lane;
        const float* e_base = ea + (((size_t)b * N_ + i) * N_) * ED_ + lane;
        const int j0 = w * 32;
#pragma unroll 8
        for (int jj = 0; jj < 32; jj++) {
            const int j = j0 + jj;
            const float a = s_a[j];
            acc_deg += a;
            acc_obs += a * __ldg(obs_base + (size_t)j * OBS_);
            if (lane < ED_) acc_e += a * __ldg(e_base + (size_t)j * ED_);
        }
        s_obs[w][lane] = acc_obs;
        if (lane < ED_) s_e[w][lane] = acc_e;
        if (lane == 0) s_deg[w] = acc_deg;
        __syncthreads();

        // combine warp partials (tids 0..40)
        if (tid < 32) {
            float s = 0.f;
#pragma unroll
            for (int q = 0; q < NW_; q++) s += s_obs[q][tid];
            fin[9 + tid] = s;
        } else if (tid < 40) {
            const int e = tid - 32;
            float s = 0.f;
#pragma unroll
            for (int q = 0; q < NW_; q++) s += s_e[q][e];
            fin[1 + e] = s;
        } else if (tid == 40) {
            float s = 0.f;
#pragma unroll
            for (int q = 0; q < NW_; q++) s += s_deg[q];
            fin[0] = s;
        }
        __syncthreads();

        if (tid < D_) {
            // tk[k] = eagg @ we1 + deg*be1 (folds (..+be)@W3 bias path)
            float s = fin[0] * ge_be[D_ + tid];
#pragma unroll
            for (int e = 0; e < ED_; e++)
                s += fin[1 + e] * ge_we[ED_ * D_ + e * D_ + tid];
            stk[tid] = s;
            // xi = obs_all[b,i,:] @ w_obs + b_obs
            float x = b_obs[tid];
            const float* orow = obs_all + ((size_t)b * N_ + i) * OBS_;
#pragma unroll
            for (int s2 = 0; s2 < OBS_; s2++) x += orow[s2] * w_obs[s2 * D_ + tid];
            sxi[tid] = x;
        }
        __syncwarp(0xffffffffu);

        if (tid < D_) {
            const int d = tid;
            const float deg = fin[0];
            float val = res_b[D_ + d] + deg * ge_bemb[D_ + d];
            float xw1 = 0.f;
#pragma unroll
            for (int k = 0; k < D_; k++) {
                val += sxi[k] * res_w[256 + k * D_ + d];  // res_w[1]
                xw1 += sxi[k] * W1[k * D_ + d];
            }
            val += deg * xw1;
            // av = sobs @ (w_obs@W2) + deg*(b_obs@W2)
            float bW2 = 0.f;
#pragma unroll
            for (int k = 0; k < D_; k++) bW2 += b_obs[k] * W2[k * D_ + d];
            float av = deg * bW2;
#pragma unroll
            for (int s = 0; s < OBS_; s++) av += fin[9 + s] * sC[s * D_ + d];
            val += av;
            float eproj = 0.f;
#pragma unroll
            for (int k = 0; k < D_; k++) eproj += stk[k] * W3[k * D_ + d];
            val += eproj;
            g_sel[b * (M_ * D_) + m * D_ + d] = fmaxf(val, 0.0f);
        }
    } else {
        if (tid < D_) g_sel[b * (M_ * D_) + m * D_ + tid] = -1.0f;
    }

    // ---- last-block-done gate ----
    __threadfence();
    __shared__ int is_last;
    if (tid == 0) {
        unsigned int c = atomicAdd(&g_count, 1u);
        is_last = (c == (unsigned int)(gridDim.x - 1));
        if (is_last) atomicExch(&g_count, 0u);  // reset for graph replay
    }
    __syncthreads();
    if (!is_last || tid >= 256) return;

    // ===================== fused head (warps 0..7, warp per b) ==============
    {
        const int hb = tid >> 5;
        const int lane = tid & 31;
        __shared__ float cat[B_][192];
        __shared__ float h0[B_][D_];
        __shared__ float h1[B_][H_];
        __shared__ float h2[B_][H_];

        for (int k = lane; k < 96; k += 32) {
            float s = b_src[k];
#pragma unroll 8
            for (int q = 0; q < SRC_; q++) s += obs[hb * SRC_ + q] * w_src[q * 96 + k];
            cat[hb][k] = s;
        }
        for (int k = lane; k < 96; k += 32) cat[hb][96 + k] = g_sel[hb * 96 + k];
        __syncwarp();

        {
            float s = gated_b[lane];
            for (int q = 0; q < 192; q++) s += cat[hb][q] * gated_w[q * 32 + lane];
            float other = __shfl_sync(0xffffffffu, s, lane ^ 16);
            if (lane < D_) h0[hb][lane] = s * (1.0f / (1.0f + expf(-other)));
        }
        __syncwarp();

        for (int k = lane; k < H_; k += 32) {
            float s = bb1[k];
#pragma unroll
            for (int d = 0; d < D_; d++) s += h0[hb][d] * bw1[d * H_ + k];
            h1[hb][k] = fmaxf(s, 0.0f);
        }
        __syncwarp();

        for (int k = lane; k < H_; k += 32) {
            float s = bb2[k];
#pragma unroll 8
            for (int j = 0; j < H_; j++) s += h1[hb][j] * bw2[j * H_ + k];
            h2[hb][k] = fmaxf(s, 0.0f);
        }
        __syncwarp();

        if (lane < M_) {
            float s = act_b[lane];
#pragma unroll 8
            for (int j = 0; j < H_; j++) s += h2[hb][j] * act_w[j * M_ + lane];
            out[hb * M_ + lane] = s;
        }
    }
}

// ---------------------------------------------------------------------------
extern "C" void kernel_launch(void* const* d_in, const int* in_sizes, int n_in,
                              void* d_out, int out_size) {
    const float* obs       = (const float*)d_in[0];
    const float* obs_all   = (const float*)d_in[1];
    const float* edge      = (const float*)d_in[2];
    const int*   ridxs     = (const int*)  d_in[3];
    const int*   nbr_idx   = (const int*)  d_in[4];
    const int*   nbr_mask  = (const int*)  d_in[5];
    const float* A         = (const float*)d_in[6];
    const float* PA        = (const float*)d_in[7];
    const float* w_src     = (const float*)d_in[8];
    const float* b_src     = (const float*)d_in[9];
    const float* w_obs     = (const float*)d_in[10];
    const float* b_obs     = (const float*)d_in[11];
    const float* res_w     = (const float*)d_in[12];
    const float* res_b     = (const float*)d_in[13];
    const float* ge_we     = (const float*)d_in[14];
    const float* ge_be     = (const float*)d_in[15];
    const float* ge_wemb   = (const float*)d_in[16];
    const float* ge_bemb   = (const float*)d_in[17];
    const float* gated_w   = (const float*)d_in[18];
    const float* gated_b   = (const float*)d_in[19];
    const float* base_w1   = (const float*)d_in[20];
    const float* base_b1   = (const float*)d_in[21];
    const float* base_w2   = (const float*)d_in[22];
    const float* base_b2   = (const float*)d_in[23];
    const float* act_w     = (const float*)d_in[24];
    const float* act_b     = (const float*)d_in[25];
    float* out = (float*)d_out;

    k_fused<<<B_ * M_, 512>>>(obs, obs_all, edge, ridxs, nbr_idx, nbr_mask,
                              A, PA, w_src, b_src, w_obs, b_obs,
                              res_w, res_b, ge_we, ge_be, ge_wemb, ge_bemb,
                              gated_w, gated_b, base_w1, base_b1,
                              base_w2, base_b2, act_w, act_b, out);
}

// round 4
// speedup vs baseline: 1.8632x; 1.2145x over previous
#include <cuda_runtime.h>
#include <cuda_bf16.h>
#include <math.h>

#define B_ 8
#define N_ 512
#define M_ 6
#define ED_ 8
#define SRC_ 64
#define OBS_ 32
#define D_ 16
#define H_ 64
#define NW_ 16

__device__ float g_sel[B_ * M_ * D_];
__device__ unsigned int g_cnt[B_];  // per-batch arrival counters (self-resetting)

// ---------------------------------------------------------------------------
// 48 blocks x 512 threads. Block (b,m) computes x_adapt row
// i = nbr_idx[ridxs[b]][m] (only the i=1 GNN layer survives in the reference).
// Block (b,0) additionally runs the per-b gated-MLP head after a per-b spin,
// with all head weights pre-staged before the spin.
// ---------------------------------------------------------------------------
__global__ void __launch_bounds__(512, 1)
k_fused(const float* __restrict__ obs,
        const float* __restrict__ obs_all,
        const float* __restrict__ ea,
        const int* __restrict__ ridxs,
        const int* __restrict__ nbr_idx,
        const int* __restrict__ nbr_mask,
        const float* __restrict__ A,
        const float* __restrict__ PA,
        const float* __restrict__ w_src,
        const float* __restrict__ b_src,
        const float* __restrict__ w_obs,
        const float* __restrict__ b_obs,
        const float* __restrict__ res_w,
        const float* __restrict__ res_b,
        const float* __restrict__ ge_we,
        const float* __restrict__ ge_be,
        const float* __restrict__ ge_wemb,
        const float* __restrict__ ge_bemb,
        const float* __restrict__ gated_w,
        const float* __restrict__ gated_b,
        const float* __restrict__ bw1,
        const float* __restrict__ bb1,
        const float* __restrict__ bw2,
        const float* __restrict__ bb2,
        const float* __restrict__ act_w,
        const float* __restrict__ act_b,
        float* __restrict__ out) {
    const int b = blockIdx.x / M_;
    const int m = blockIdx.x % M_;
    const int tid = threadIdx.x;
    const int lane = tid & 31;
    const int w = tid >> 5;
    const int r = ridxs[b];
    const int i = nbr_idx[r * M_ + m];
    const int msk = nbr_mask[r * M_ + m];

    const float* W1 = ge_wemb + 768;
    const float* W2 = ge_wemb + 768 + 256;
    const float* W3 = ge_wemb + 768 + 512;

    // --- reduction shared ---
    __shared__ float s_a[N_];
    __shared__ float sC[OBS_ * D_];
    __shared__ float s_obs[NW_][33];
    __shared__ float s_e[NW_][32];
    __shared__ float fin[41];  // [0]=deg [1..8]=eagg [9..40]=sobs
    __shared__ float stk[D_], sxi[D_];
    // --- head shared (only used by m==0 blocks) ---
    __shared__ float s_cat[192];
    __shared__ float s_gp[32 * 16];
    __shared__ float s_h0[D_], s_h1[H_], s_h2[H_];
    __shared__ float s_bw1[D_ * H_];
    __shared__ float s_bw2[H_ * H_];
    __shared__ float s_act[H_ * M_];
    __shared__ float s_actb[M_];

    if (msk != 0) {
        s_a[tid] = A[i * N_ + tid] + PA[i * N_ + tid];
        {
            const int s = tid >> 4, d = tid & 15;
            float acc = 0.f;
#pragma unroll
            for (int k = 0; k < D_; k++) acc += w_obs[s * D_ + k] * W2[k * D_ + d];
            sC[tid] = acc;
        }
        __syncthreads();

        const int j0 = w * 32;
        // obs: lane = feature, fully unrolled: 32 independent coalesced LDGs
        float acc_obs = 0.f;
        const float* orow = obs_all + ((size_t)b * N_ + j0) * OBS_ + lane;
#pragma unroll
        for (int jj = 0; jj < 32; jj++)
            acc_obs += s_a[j0 + jj] * __ldg(orow + jj * OBS_);
        // edge: lane = (j%4, e): 8 independent 128B-coalesced LDGs
        const int esub = lane >> 3, eidx = lane & 7;
        float acc_e = 0.f;
        const float* erow = ea + (((size_t)b * N_ + i) * N_ + j0 + esub) * ED_ + eidx;
#pragma unroll
        for (int g = 0; g < 8; g++)
            acc_e += s_a[j0 + g * 4 + esub] * __ldg(erow + g * 4 * ED_);
        s_obs[w][lane] = acc_obs;
        s_e[w][lane] = acc_e;
        __syncthreads();

        if (tid < 32) {            // sobs combine
            float s = 0.f;
#pragma unroll
            for (int q = 0; q < NW_; q++) s += s_obs[q][tid];
            fin[9 + tid] = s;
        } else if (tid < 40) {     // eagg combine
            const int e = tid - 32;
            float s = 0.f;
#pragma unroll
            for (int q = 0; q < NW_; q++)
#pragma unroll
                for (int g = 0; g < 4; g++) s += s_e[q][g * 8 + e];
            fin[1 + e] = s;
        } else if (tid >= 64 && tid < 96) {  // deg via warp 2
            const int l2 = tid - 64;
            float s = 0.f;
#pragma unroll
            for (int k = 0; k < NW_; k++) s += s_a[l2 + 32 * k];
#pragma unroll
            for (int off = 16; off > 0; off >>= 1)
                s += __shfl_down_sync(0xffffffffu, s, off);
            if (l2 == 0) fin[0] = s;
        }
        __syncthreads();

        if (tid < D_) {
            float s = fin[0] * ge_be[D_ + tid];
#pragma unroll
            for (int e = 0; e < ED_; e++)
                s += fin[1 + e] * ge_we[ED_ * D_ + e * D_ + tid];
            stk[tid] = s;
            float x = b_obs[tid];
            const float* orw = obs_all + ((size_t)b * N_ + i) * OBS_;
#pragma unroll
            for (int s2 = 0; s2 < OBS_; s2++) x += orw[s2] * w_obs[s2 * D_ + tid];
            sxi[tid] = x;
        }
        __syncwarp(0xffffffffu);

        if (tid < D_) {
            const int d = tid;
            const float deg = fin[0];
            float val = res_b[D_ + d] + deg * ge_bemb[D_ + d];
            float xw1 = 0.f;
#pragma unroll
            for (int k = 0; k < D_; k++) {
                val += sxi[k] * res_w[256 + k * D_ + d];
                xw1 += sxi[k] * W1[k * D_ + d];
            }
            val += deg * xw1;
            float bW2 = 0.f;
#pragma unroll
            for (int k = 0; k < D_; k++) bW2 += b_obs[k] * W2[k * D_ + d];
            float av = deg * bW2;
#pragma unroll
            for (int s = 0; s < OBS_; s++) av += fin[9 + s] * sC[s * D_ + d];
            val += av;
            float eproj = 0.f;
#pragma unroll
            for (int k = 0; k < D_; k++) eproj += stk[k] * W3[k * D_ + d];
            val += eproj;
            g_sel[b * (M_ * D_) + m * D_ + d] = fmaxf(val, 0.0f);
        }
    } else {
        if (tid < D_) g_sel[b * (M_ * D_) + m * D_ + tid] = -1.0f;
    }

    __syncthreads();
    __threadfence();
    if (tid == 0) atomicAdd(&g_cnt[b], 1u);
    if (m != 0) return;

    // =============== head block: pre-stage everything, then spin ============
    // obs_p -> cat[0..95] (independent of g_sel)
    if (tid < 96) {
        float s = b_src[tid];
#pragma unroll
        for (int q = 0; q < SRC_; q++) s += obs[b * SRC_ + q] * w_src[q * 96 + tid];
        s_cat[tid] = s;
    }
    // gated_w -> registers: thread (o=tid&31, p=tid>>5) holds 12 inputs
    const int go = tid & 31, gp = tid >> 5;
    float gw[12];
#pragma unroll
    for (int rr = 0; rr < 12; rr++) gw[rr] = gated_w[(gp * 12 + rr) * 32 + go];
    float gbias = (tid < 32) ? gated_b[tid] : 0.f;
    float bb1r = (tid < H_) ? bb1[tid] : 0.f;
    float bb2r = (tid < H_) ? bb2[tid] : 0.f;
    // bw1 / bw2 / act_w -> shared
    for (int t = tid; t < D_ * H_; t += 512) s_bw1[t] = bw1[t];
    for (int t = tid; t < H_ * H_; t += 512) s_bw2[t] = bw2[t];
    for (int t = tid; t < H_ * M_; t += 512) s_act[t] = act_w[t];
    if (tid < M_) s_actb[tid] = act_b[tid];

    // spin until all 6 row-blocks of this b arrived
    if (tid == 0) {
        volatile unsigned int* p = &g_cnt[b];
        while (*p < (unsigned int)M_) {}
        g_cnt[b] = 0;  // reset for next graph replay
        __threadfence();
    }
    __syncthreads();

    if (tid >= 96 && tid < 192) s_cat[tid] = g_sel[b * 96 + (tid - 96)];
    __syncthreads();

    // gate matmul: 32 outputs x 16 partials, 12 FMAs each (all from shared)
    {
        float s = 0.f;
#pragma unroll
        for (int rr = 0; rr < 12; rr++) s += s_cat[gp * 12 + rr] * gw[rr];
        s_gp[go * 16 + gp] = s;
    }
    __syncthreads();
    if (tid < 32) {
        float g = gbias;
#pragma unroll
        for (int p2 = 0; p2 < 16; p2++) g += s_gp[tid * 16 + p2];
        float other = __shfl_sync(0xffffffffu, g, tid ^ 16);
        if (tid < D_) s_h0[tid] = g * (1.0f / (1.0f + expf(-other)));
    }
    __syncthreads();
    if (tid < H_) {
        float s = bb1r;
#pragma unroll
        for (int d = 0; d < D_; d++) s += s_h0[d] * s_bw1[d * H_ + tid];
        s_h1[tid] = fmaxf(s, 0.0f);
    }
    __syncthreads();
    if (tid < H_) {
        float s = bb2r;
#pragma unroll
        for (int j = 0; j < H_; j++) s += s_h1[j] * s_bw2[j * H_ + tid];
        s_h2[tid] = fmaxf(s, 0.0f);
    }
    __syncthreads();
    if (tid < 192) {
        const int o = tid >> 5;  // 6 warps, one output each
        float s = s_h2[lane] * s_act[lane * M_ + o]
                + s_h2[lane + 32] * s_act[(lane + 32) * M_ + o];
#pragma unroll
        for (int off = 16; off > 0; off >>= 1)
            s += __shfl_down_sync(0xffffffffu, s, off);
        if (lane == 0) out[b * M_ + o] = s + s_actb[o];
    }
}

// ---------------------------------------------------------------------------
extern "C" void kernel_launch(void* const* d_in, const int* in_sizes, int n_in,
                              void* d_out, int out_size) {
    const float* obs       = (const float*)d_in[0];
    const float* obs_all   = (const float*)d_in[1];
    const float* edge      = (const float*)d_in[2];
    const int*   ridxs     = (const int*)  d_in[3];
    const int*   nbr_idx   = (const int*)  d_in[4];
    const int*   nbr_mask  = (const int*)  d_in[5];
    const float* A         = (const float*)d_in[6];
    const float* PA        = (const float*)d_in[7];
    const float* w_src     = (const float*)d_in[8];
    const float* b_src     = (const float*)d_in[9];
    const float* w_obs     = (const float*)d_in[10];
    const float* b_obs     = (const float*)d_in[11];
    const float* res_w     = (const float*)d_in[12];
    const float* res_b     = (const float*)d_in[13];
    const float* ge_we     = (const float*)d_in[14];
    const float* ge_be     = (const float*)d_in[15];
    const float* ge_wemb   = (const float*)d_in[16];
    const float* ge_bemb   = (const float*)d_in[17];
    const float* gated_w   = (const float*)d_in[18];
    const float* gated_b   = (const float*)d_in[19];
    const float* base_w1   = (const float*)d_in[20];
    const float* base_b1   = (const float*)d_in[21];
    const float* base_w2   = (const float*)d_in[22];
    const float* base_b2   = (const float*)d_in[23];
    const float* act_w     = (const float*)d_in[24];
    const float* act_b     = (const float*)d_in[25];
    float* out = (float*)d_out;

    k_fused<<<B_ * M_, 512>>>(obs, obs_all, edge, ridxs, nbr_idx, nbr_mask,
                              A, PA, w_src, b_src, w_obs, b_obs,
                              res_w, res_b, ge_we, ge_be, ge_wemb, ge_bemb,
                              gated_w, gated_b, base_w1, base_b1,
                              base_w2, base_b2, act_w, act_b, out);
}

// round 5
// speedup vs baseline: 2.7167x; 1.4581x over previous
#include <cuda_runtime.h>
#include <cuda_bf16.h>
#include <math.h>

#define B_ 8
#define N_ 512
#define M_ 6
#define ED_ 8
#define SRC_ 64
#define OBS_ 32
#define D_ 16
#define H_ 64
#define NW_ 16

// ---------------------------------------------------------------------------
// 8 blocks x 512 threads; block b handles batch b end-to-end (6 GNN rows +
// gated-MLP head). Only the i=1 GNN layer survives in the reference (the i=0
// loop iteration is dead), and the per-node embedding is folded analytically:
//   sum_j a_ij (x@W2)[b,j] = (sum_j a_ij obs_all[b,j]) @ (w_obs@W2) + deg*(b_obs@W2)
// No global scratch, no cross-block sync.
// ---------------------------------------------------------------------------
__global__ void __launch_bounds__(512, 1)
k_fused(const float* __restrict__ obs,
        const float* __restrict__ obs_all,
        const float* __restrict__ ea,
        const int* __restrict__ ridxs,
        const int* __restrict__ nbr_idx,
        const int* __restrict__ nbr_mask,
        const float* __restrict__ A,
        const float* __restrict__ PA,
        const float* __restrict__ w_src,
        const float* __restrict__ b_src,
        const float* __restrict__ w_obs,
        const float* __restrict__ b_obs,
        const float* __restrict__ res_w,
        const float* __restrict__ res_b,
        const float* __restrict__ ge_we,
        const float* __restrict__ ge_be,
        const float* __restrict__ ge_wemb,
        const float* __restrict__ ge_bemb,
        const float* __restrict__ gated_w,
        const float* __restrict__ gated_b,
        const float* __restrict__ bw1,
        const float* __restrict__ bb1,
        const float* __restrict__ bw2,
        const float* __restrict__ bb2,
        const float* __restrict__ act_w,
        const float* __restrict__ act_b,
        float* __restrict__ out) {
    const int b = blockIdx.x;
    const int tid = threadIdx.x;
    const int lane = tid & 31;
    const int w = tid >> 5;

    const float* W1 = ge_wemb + 768;
    const float* W2 = ge_wemb + 768 + 256;
    const float* W3 = ge_wemb + 768 + 512;

    __shared__ int s_i[M_], s_msk[M_];
    __shared__ float s_a[M_][N_];            // 12 KB
    __shared__ float sC[OBS_ * D_];          // 2 KB  (w_obs @ W2)
    __shared__ float s_po[NW_][M_][33];      // 12.7 KB obs partials
    __shared__ float s_pe[NW_][M_][32];      // 12 KB  edge partials
    __shared__ float s_pd[NW_][M_];          // deg partials
    __shared__ float fin[M_][41];            // [0]=deg [1..8]=eagg [9..40]=sobs
    __shared__ float stk[M_][D_], sxi[M_][D_];
    __shared__ float s_cat[192];
    __shared__ float s_gp[32 * 16];
    __shared__ float s_lp[H_][4];
    __shared__ float s_h0[D_], s_h1[H_], s_h2[H_];
    __shared__ float s_act[H_ * M_];
    __shared__ float s_actb[M_];

    // --- indices (dependent chase, 6 threads) ---
    if (tid < M_) {
        const int r = __ldg(&ridxs[b]);
        s_i[tid] = __ldg(&nbr_idx[r * M_ + tid]);
        s_msk[tid] = __ldg(&nbr_mask[r * M_ + tid]);
    }
    __syncthreads();

    // --- stage 6 adjacency rows + sC ---
#pragma unroll
    for (int m = 0; m < M_; m++)
        s_a[m][tid] = __ldg(&A[s_i[m] * N_ + tid]) + __ldg(&PA[s_i[m] * N_ + tid]);
    {
        const int s = tid >> 4, d = tid & 15;
        float acc = 0.f;
#pragma unroll
        for (int k = 0; k < D_; k++) acc += w_obs[s * D_ + k] * W2[k * D_ + d];
        sC[tid] = acc;
    }
    __syncthreads();

    // --- main j-loop: warp w covers j in [32w, 32w+32) for all 6 rows ---
    {
        const int j0 = w * 32;
        float acc_o[M_], acc_e[M_], accd[M_];
#pragma unroll
        for (int m = 0; m < M_; m++) {
            acc_o[m] = 0.f; acc_e[m] = 0.f;
            accd[m] = s_a[m][j0 + lane];  // one j per lane -> deg
        }
        const float* obase = obs_all + ((size_t)b * N_ + j0) * OBS_ + lane;
#pragma unroll
        for (int jj = 0; jj < 32; jj++) {
            const float v = __ldg(obase + jj * OBS_);
#pragma unroll
            for (int m = 0; m < M_; m++) acc_o[m] += s_a[m][j0 + jj] * v;
        }
        const int esub = lane >> 3, eidx = lane & 7;
        const float* eb = ea + ((size_t)b * N_) * (N_ * ED_) + (j0 + esub) * ED_ + eidx;
#pragma unroll
        for (int g = 0; g < 8; g++) {
#pragma unroll
            for (int m = 0; m < M_; m++)
                acc_e[m] += s_a[m][j0 + g * 4 + esub] *
                            __ldg(eb + (size_t)s_i[m] * (N_ * ED_) + g * 4 * ED_);
        }
#pragma unroll
        for (int m = 0; m < M_; m++) {
            s_po[w][m][lane] = acc_o[m];
            s_pe[w][m][lane] = acc_e[m];
#pragma unroll
            for (int off = 16; off > 0; off >>= 1)
                accd[m] += __shfl_down_sync(0xffffffffu, accd[m], off);
        }
        if (lane == 0)
#pragma unroll
            for (int m = 0; m < M_; m++) s_pd[w][m] = accd[m];
    }
    __syncthreads();

    // --- combine partials (246 thr) || obs_p (96 thr) ---
    if (tid < M_ * 41) {
        const int m = tid / 41, q = tid % 41;
        float s = 0.f;
        if (q == 0) {
#pragma unroll
            for (int q2 = 0; q2 < NW_; q2++) s += s_pd[q2][m];
        } else if (q < 9) {
            const int e = q - 1;
#pragma unroll
            for (int q2 = 0; q2 < NW_; q2++)
#pragma unroll
                for (int g = 0; g < 4; g++) s += s_pe[q2][m][g * 8 + e];
        } else {
            const int sf = q - 9;
#pragma unroll
            for (int q2 = 0; q2 < NW_; q2++) s += s_po[q2][m][sf];
        }
        fin[m][q] = s;
    } else if (tid >= 256 && tid < 352) {
        const int k = tid - 256;
        float s = __ldg(&b_src[k]);
#pragma unroll
        for (int q = 0; q < SRC_; q++) s += __ldg(&obs[b * SRC_ + q]) * __ldg(&w_src[q * 96 + k]);
        s_cat[k] = s;
    }
    __syncthreads();

    // --- tail phase A: stk/sxi + head weight prefetch (parallel) ---
    const int go = tid & 31, gp = tid >> 5;
    float gw[12];
#pragma unroll
    for (int rr = 0; rr < 12; rr++) gw[rr] = __ldg(&gated_w[(gp * 12 + rr) * 32 + go]);
    const float gbias = (tid < 32) ? __ldg(&gated_b[tid]) : 0.f;
    float bwr[16];   // bw2 column (tid<256): rows (tid>>6)*16.., col tid&63
    if (tid < 256) {
        const int k = tid & 63, p = tid >> 6;
#pragma unroll
        for (int j = 0; j < 16; j++) bwr[j] = __ldg(&bw2[(p * 16 + j) * H_ + k]);
    }
    float bw1r[16];  // bw1 column (tid in [256,320))
    float bb1r = 0.f;
    if (tid >= 256 && tid < 320) {
        const int k = tid - 256;
#pragma unroll
        for (int d = 0; d < D_; d++) bw1r[d] = __ldg(&bw1[d * H_ + k]);
        bb1r = __ldg(&bb1[k]);
    }
    const float bb2r = (tid < 64) ? __ldg(&bb2[tid]) : 0.f;
    if (tid >= 352) {
        for (int t = tid - 352; t < H_ * M_; t += 160) s_act[t] = __ldg(&act_w[t]);
        if (tid - 352 < M_) s_actb[tid - 352] = __ldg(&act_b[tid - 352]);
    }
    if (tid < 96) {
        const int m = tid >> 4, d = tid & 15;
        float s = fin[m][0] * __ldg(&ge_be[D_ + d]);
#pragma unroll
        for (int e = 0; e < ED_; e++)
            s += fin[m][1 + e] * __ldg(&ge_we[ED_ * D_ + e * D_ + d]);
        stk[m][d] = s;
        float x = __ldg(&b_obs[d]);
        const float* orw = obs_all + ((size_t)b * N_ + s_i[m]) * OBS_;
#pragma unroll
        for (int s2 = 0; s2 < OBS_; s2++) x += __ldg(&orw[s2]) * __ldg(&w_obs[s2 * D_ + d]);
        sxi[m][d] = x;
    }
    __syncthreads();

    // --- tail phase B: final x_adapt values straight into cat ---
    if (tid < 96) {
        const int m = tid >> 4, d = tid & 15;
        float res = -1.0f;
        if (s_msk[m] != 0) {
            const float deg = fin[m][0];
            float val = __ldg(&res_b[D_ + d]) + deg * __ldg(&ge_bemb[D_ + d]);
            float xw1 = 0.f;
#pragma unroll
            for (int k = 0; k < D_; k++) {
                val += sxi[m][k] * __ldg(&res_w[256 + k * D_ + d]);
                xw1 += sxi[m][k] * __ldg(&W1[k * D_ + d]);
            }
            val += deg * xw1;
            float bW2 = 0.f;
#pragma unroll
            for (int k = 0; k < D_; k++) bW2 += __ldg(&b_obs[k]) * __ldg(&W2[k * D_ + d]);
            float av = deg * bW2;
#pragma unroll
            for (int s = 0; s < OBS_; s++) av += fin[m][9 + s] * sC[s * D_ + d];
            val += av;
            float ep = 0.f;
#pragma unroll
            for (int k = 0; k < D_; k++) ep += stk[m][k] * __ldg(&W3[k * D_ + d]);
            val += ep;
            res = fmaxf(val, 0.0f);
        }
        s_cat[96 + tid] = res;
    }
    __syncthreads();

    // --- gate: 32 outputs x 16 partials, regs+shared only ---
    {
        float s = 0.f;
#pragma unroll
        for (int rr = 0; rr < 12; rr++) s += s_cat[gp * 12 + rr] * gw[rr];
        s_gp[go * 16 + gp] = s;
    }
    __syncthreads();
    if (tid < 32) {
        float g = gbias;
#pragma unroll
        for (int p2 = 0; p2 < 16; p2++) g += s_gp[tid * 16 + p2];
        const float other = __shfl_sync(0xffffffffu, g, tid ^ 16);
        if (tid < D_) s_h0[tid] = g * (1.0f / (1.0f + expf(-other)));
    }
    __syncthreads();
    // --- layer 1 (weights already in regs of tids 256..319) ---
    if (tid >= 256 && tid < 320) {
        const int k = tid - 256;
        float s = bb1r;
#pragma unroll
        for (int d = 0; d < D_; d++) s += s_h0[d] * bw1r[d];
        s_h1[k] = fmaxf(s, 0.0f);
    }
    __syncthreads();
    // --- layer 2: 64 outputs x 4 partials (weights in regs of tids 0..255) ---
    if (tid < 256) {
        const int k = tid & 63, p = tid >> 6;
        float s = 0.f;
#pragma unroll
        for (int j = 0; j < 16; j++) s += s_h1[p * 16 + j] * bwr[j];
        s_lp[k][p] = s;
    }
    __syncthreads();
    if (tid < 64) {
        float s = bb2r;
#pragma unroll
        for (int p = 0; p < 4; p++) s += s_lp[tid][p];
        s_h2[tid] = fmaxf(s, 0.0f);
    }
    __syncthreads();
    // --- output: 6 warps, one output each ---
    if (tid < 192) {
        const int o = tid >> 5;
        float s = s_h2[lane] * s_act[lane * M_ + o]
                + s_h2[lane + 32] * s_act[(lane + 32) * M_ + o];
#pragma unroll
        for (int off = 16; off > 0; off >>= 1)
            s += __shfl_down_sync(0xffffffffu, s, off);
        if (lane == 0) out[b * M_ + o] = s + s_actb[o];
    }
}

// ---------------------------------------------------------------------------
extern "C" void kernel_launch(void* const* d_in, const int* in_sizes, int n_in,
                              void* d_out, int out_size) {
    const float* obs       = (const float*)d_in[0];
    const float* obs_all   = (const float*)d_in[1];
    const float* edge      = (const float*)d_in[2];
    const int*   ridxs     = (const int*)  d_in[3];
    const int*   nbr_idx   = (const int*)  d_in[4];
    const int*   nbr_mask  = (const int*)  d_in[5];
    const float* A         = (const float*)d_in[6];
    const float* PA        = (const float*)d_in[7];
    const float* w_src     = (const float*)d_in[8];
    const float* b_src     = (const float*)d_in[9];
    const float* w_obs     = (const float*)d_in[10];
    const float* b_obs     = (const float*)d_in[11];
    const float* res_w     = (const float*)d_in[12];
    const float* res_b     = (const float*)d_in[13];
    const float* ge_we     = (const float*)d_in[14];
    const float* ge_be     = (const float*)d_in[15];
    const float* ge_wemb   = (const float*)d_in[16];
    const float* ge_bemb   = (const float*)d_in[17];
    const float* gated_w   = (const float*)d_in[18];
    const float* gated_b   = (const float*)d_in[19];
    const float* base_w1   = (const float*)d_in[20];
    const float* base_b1   = (const float*)d_in[21];
    const float* base_w2   = (const float*)d_in[22];
    const float* base_b2   = (const float*)d_in[23];
    const float* act_w     = (const float*)d_in[24];
    const float* act_b     = (const float*)d_in[25];
    float* out = (float*)d_out;

    k_fused<<<B_, 512>>>(obs, obs_all, edge, ridxs, nbr_idx, nbr_mask,
                         A, PA, w_src, b_src, w_obs, b_obs,
                         res_w, res_b, ge_we, ge_be, ge_wemb, ge_bemb,
                         gated_w, gated_b, base_w1, base_b1,
                         base_w2, base_b2, act_w, act_b, out);
}